// round 10
// baseline (speedup 1.0000x reference)
#include <cuda_runtime.h>
#include <math.h>
#include <stdint.h>

#define THREADS   128
#define IMGS      128          // images per block, 2 per thread
#define NP        129          // float4 stride per v-row (odd -> conflict-free)
#define PX_F4     (14 * NP)    // 1806 float4, single buffer
#define SMEM_BYTES (PX_F4 * 16)   // 28896 B -> 4 CTAs/SM

typedef unsigned long long ull;

__device__ __forceinline__ void fma2(ull &acc, ull a, ull b) {
    asm("fma.rn.f32x2 %0, %1, %2, %0;" : "+l"(acc) : "l"(a), "l"(b));
}
__device__ __forceinline__ ull pack2(float lo, float hi) {
    ull r; asm("mov.b64 %0, {%1, %2};" : "=l"(r) : "f"(lo), "f"(hi)); return r;
}
__device__ __forceinline__ float2 unpack2(ull v) {
    float lo, hi; asm("mov.b64 {%0, %1}, %2;" : "=f"(lo), "=f"(hi) : "l"(v));
    return make_float2(lo, hi);
}

// one patch-row tile, two images (slots p and p+64), cols CB..CB+6.
// W read via uniform LDG (L1-resident, 1 wavefront per load).
template<int CB>
__device__ __forceinline__ void compute_tile(const float4* __restrict__ px,
                                             const ulonglong2* __restrict__ wbase,
                                             int p, ull* accA, ull* accB)
{
    #pragma unroll
    for (int cc = 0; cc < 7; cc++) {
        const int c  = CB + cc;          // compile-time
        const int vA = c >> 1;           // float4 shared by cols 2vA, 2vA+1
        const int vB = 7 + vA;
        float4 a0 = px[vA * NP + p];         // img0, row 2r
        float4 a1 = px[vA * NP + 64 + p];    // img1, row 2r
        float4 b0 = px[vB * NP + p];         // img0, row 2r+1
        float4 b1 = px[vB * NP + 64 + p];    // img1, row 2r+1
        float x00_0, x01_0, x10_0, x11_0, x00_1, x01_1, x10_1, x11_1;
        if ((c & 1) == 0) {
            x00_0 = a0.x; x01_0 = a0.y; x10_0 = b0.x; x11_0 = b0.y;
            x00_1 = a1.x; x01_1 = a1.y; x10_1 = b1.x; x11_1 = b1.y;
        } else {
            x00_0 = a0.z; x01_0 = a0.w; x10_0 = b0.z; x11_0 = b0.w;
            x00_1 = a1.z; x01_1 = a1.w; x10_1 = b1.z; x11_1 = b1.w;
        }
        float e0a = __cosf(x00_0);
        float e1a = e0a * __cosf(x01_0);
        float e2a = e1a * __cosf(x10_0);
        float e3a = e2a * __cosf(x11_0);
        float e0b = __cosf(x00_1);
        float e1b = e0b * __cosf(x01_1);
        float e2b = e1b * __cosf(x10_1);
        float e3b = e2b * __cosf(x11_1);
        ull eA01 = pack2(e0a, e1a), eA23 = pack2(e2a, e3a);
        ull eB01 = pack2(e0b, e1b), eB23 = pack2(e2b, e3b);
        const ulonglong2* wrow = wbase + c;
        #pragma unroll
        for (int o = 0; o < 10; o++) {
            ulonglong2 w = wrow[o * 196];    // uniform LDG.128, L1 hit
            fma2(accA[o], eA01, w.x);
            fma2(accA[o], eA23, w.y);
            fma2(accB[o], eB01, w.x);
            fma2(accB[o], eB23, w.y);
        }
    }
}

__global__ void __launch_bounds__(THREADS, 4)
quanv_kernel(const float* __restrict__ x,
             const float* __restrict__ W,
             const float* __restrict__ b,
             float* __restrict__ out)
{
    extern __shared__ float smem[];
    float4* s_px = (float4*)smem;    // [14][NP] float4, single buffer
    float*  s_mg = smem;             // epilogue merge aliases px buffer

    const int tid   = threadIdx.x;
    const int p     = tid & 63;      // image-pair index (imgs 2p, 2p+1)
    const int chalf = tid >> 6;      // 0: cols 0..6, 1: cols 7..13 (warp-uniform)

    const long imgBase = (long)blockIdx.x * IMGS;
    const float* xg = x + imgBase * 784;

    // granule mapping base (j = tid + 128*it):  img = j/14, v = j%14
    const int v0   = tid % 14;
    const int img0 = tid / 14;
    const int off0 = img0 * 784 + v0 * 4;    // float offset at it=0 (add r*56/tile)

    // prefetch tile 0 into registers
    float4 stage[14];
    {
        int v = v0, off = off0;
        #pragma unroll
        for (int it = 0; it < 14; it++) {
            stage[it] = *(const float4*)(xg + off);
            off += 7064; v += 2;                 // j += 128
            if (v >= 14) { v -= 14; off += 728; }
        }
    }

    ull accA[10], accB[10];
    #pragma unroll
    for (int o = 0; o < 10; o++) { accA[o] = 0ull; accB[o] = 0ull; }

    #pragma unroll 1
    for (int r = 0; r < 14; r++) {
        // store staged tile (14 STS.128), dst index recomputed incrementally
        {
            int v = v0, img = img0;
            #pragma unroll
            for (int it = 0; it < 14; it++) {
                int pos = ((img & 1) << 6) | (img >> 1);   // pair-split permutation
                s_px[v * NP + pos] = stage[it];
                v += 2; img += 9;
                if (v >= 14) { v -= 14; img++; }
            }
        }
        __syncthreads();

        // prefetch next tile — LDG latency hidden behind compute
        if (r < 13) {
            const float* srcT = xg + (r + 1) * 56;
            int v = v0, off = off0;
            #pragma unroll
            for (int it = 0; it < 14; it++) {
                stage[it] = *(const float4*)(srcT + off);
                off += 7064; v += 2;
                if (v >= 14) { v -= 14; off += 728; }
            }
        }

        const ulonglong2* wbase = (const ulonglong2*)W + r * 14;
        if (chalf == 0) compute_tile<0>(s_px, wbase, p, accA, accB);
        else            compute_tile<7>(s_px, wbase, p, accA, accB);
        __syncthreads();
    }

    // reduce f32x2 (even/odd k) lanes
    float sA[10], sB[10];
    #pragma unroll
    for (int o = 0; o < 10; o++) {
        float2 a = unpack2(accA[o]); sA[o] = a.x + a.y;
        float2 c = unpack2(accB[o]); sB[o] = c.x + c.y;
    }

    // merge the two column-halves via shared (stride 21 per image slot)
    if (chalf == 1) {
        #pragma unroll
        for (int o = 0; o < 10; o++) {
            s_mg[p * 42 + o]      = sA[o];
            s_mg[p * 42 + 21 + o] = sB[o];
        }
    }
    __syncthreads();

    if (chalf == 0) {
        float l[20];
        #pragma unroll
        for (int o = 0; o < 10; o++) {
            float bias = __ldg(b + o);
            l[o]      = sA[o] + s_mg[p * 42 + o]      + bias;
            l[10 + o] = sB[o] + s_mg[p * 42 + 21 + o] + bias;
        }
        #pragma unroll
        for (int im = 0; im < 2; im++) {
            float m = -INFINITY;
            #pragma unroll
            for (int o = 0; o < 10; o++) m = fmaxf(m, l[im * 10 + o]);
            float s = 0.f;
            #pragma unroll
            for (int o = 0; o < 10; o++) s += __expf(l[im * 10 + o] - m);
            float lse = m + __logf(s);
            #pragma unroll
            for (int o = 0; o < 10; o++) l[im * 10 + o] -= lse;
        }
        float4* op = (float4*)(out + (imgBase + 2 * p) * 10);   // 20 floats, 16B aligned
        #pragma unroll
        for (int q = 0; q < 5; q++)
            op[q] = make_float4(l[q * 4], l[q * 4 + 1], l[q * 4 + 2], l[q * 4 + 3]);
    }
}

extern "C" void kernel_launch(void* const* d_in, const int* in_sizes, int n_in,
                              void* d_out, int out_size)
{
    const float* x = (const float*)d_in[0];
    const float* W = (const float*)d_in[1];
    const float* b = (const float*)d_in[2];
    float* out = (float*)d_out;

    const int B = in_sizes[0] / 784;    // 65536
    const int grid = B / IMGS;          // 512  (<= 592 slots at 4 CTAs/SM: one wave)

    cudaFuncSetAttribute(quanv_kernel,
                         cudaFuncAttributeMaxDynamicSharedMemorySize, SMEM_BYTES);
    quanv_kernel<<<grid, THREADS, SMEM_BYTES>>>(x, W, b, out);
}

// round 11
// speedup vs baseline: 1.7149x; 1.7149x over previous
#include <cuda_runtime.h>
#include <math.h>
#include <stdint.h>

#define THREADS   128
#define IMGS      128
#define NP        129                  // float4 stride per v-row (odd -> conflict-free)
#define PX_F4     (14 * NP)            // 1806 float4, single buffer
#define SMEM_BYTES (PX_F4 * 16)        // 28896 B -> 4 CTAs/SM

typedef unsigned long long ull;

// W repacked: for GEMM k (0..783), 3 ulonglong2 per k:
//   cW2[k*3+0] = ((W[0][k],W[1][k]),(W[2][k],W[3][k]))
//   cW2[k*3+1] = ((W[4][k],W[5][k]),(W[6][k],W[7][k]))
//   cW2[k*3+2] = ((W[8][k],W[9][k]), pad)
__constant__ ulonglong2 cW2[784 * 3];
__constant__ float      cbias[10];
__device__   ull        g_wp[784 * 6];   // prep scratch (same bytes as cW2)

__device__ __forceinline__ void fma2(ull &acc, ull a, ull b) {
    asm("fma.rn.f32x2 %0, %1, %2, %0;" : "+l"(acc) : "l"(a), "l"(b));
}
__device__ __forceinline__ ull pack2(float lo, float hi) {
    ull r; asm("mov.b64 %0, {%1, %2};" : "=l"(r) : "f"(lo), "f"(hi)); return r;
}
__device__ __forceinline__ float2 unpack2(ull v) {
    float lo, hi; asm("mov.b64 {%0, %1}, %2;" : "=f"(lo), "=f"(hi) : "l"(v));
    return make_float2(lo, hi);
}

__global__ void prep_kernel(const float* __restrict__ W) {
    int i = blockIdx.x * blockDim.x + threadIdx.x;   // 0..4703
    if (i < 784 * 6) {
        int k = i / 6, oq = i - 6 * k;               // oq = o-pair slot 0..5 (5 = pad)
        ull v = 0ull;
        if (oq < 5) {
            uint32_t lo = __float_as_uint(W[(2 * oq)     * 784 + k]);
            uint32_t hi = __float_as_uint(W[(2 * oq + 1) * 784 + k]);
            v = ((ull)hi << 32) | lo;
        }
        g_wp[i] = v;
    }
}

// one patch-row tile, two images (slots p, p+64), cols CB..CB+6
template<int CB>
__device__ __forceinline__ void compute_tile(const float4* __restrict__ px,
                                             int r, int p, ull* accA, ull* accB)
{
    #pragma unroll
    for (int cc = 0; cc < 7; cc++) {
        const int c  = CB + cc;          // compile-time
        const int vA = c >> 1;
        const int vB = 7 + vA;
        float4 a0 = px[vA * NP + p];
        float4 a1 = px[vA * NP + 64 + p];
        float4 b0 = px[vB * NP + p];
        float4 b1 = px[vB * NP + 64 + p];
        float x00_0, x01_0, x10_0, x11_0, x00_1, x01_1, x10_1, x11_1;
        if ((c & 1) == 0) {
            x00_0 = a0.x; x01_0 = a0.y; x10_0 = b0.x; x11_0 = b0.y;
            x00_1 = a1.x; x01_1 = a1.y; x10_1 = b1.x; x11_1 = b1.y;
        } else {
            x00_0 = a0.z; x01_0 = a0.w; x10_0 = b0.z; x11_0 = b0.w;
            x00_1 = a1.z; x01_1 = a1.w; x10_1 = b1.z; x11_1 = b1.w;
        }
        float ea[4], eb[4];
        ea[0] = __cosf(x00_0);
        ea[1] = ea[0] * __cosf(x01_0);
        ea[2] = ea[1] * __cosf(x10_0);
        ea[3] = ea[2] * __cosf(x11_0);
        eb[0] = __cosf(x00_1);
        eb[1] = eb[0] * __cosf(x01_1);
        eb[2] = eb[1] * __cosf(x10_1);
        eb[3] = eb[2] * __cosf(x11_1);

        const int kb3 = (r * 56 + c * 4) * 3;    // ull2 index of k = 4*(r*14+c), j=0
        #pragma unroll
        for (int j = 0; j < 4; j++) {
            ulonglong2 w01 = cW2[kb3 + j * 3];       // uniform const loads
            ulonglong2 w23 = cW2[kb3 + j * 3 + 1];
            ulonglong2 w4p = cW2[kb3 + j * 3 + 2];
            ull da = pack2(ea[j], ea[j]);
            ull db = pack2(eb[j], eb[j]);
            fma2(accA[0], da, w01.x);
            fma2(accA[1], da, w01.y);
            fma2(accA[2], da, w23.x);
            fma2(accA[3], da, w23.y);
            fma2(accA[4], da, w4p.x);
            fma2(accB[0], db, w01.x);
            fma2(accB[1], db, w01.y);
            fma2(accB[2], db, w23.x);
            fma2(accB[3], db, w23.y);
            fma2(accB[4], db, w4p.x);
        }
    }
}

__global__ void __launch_bounds__(THREADS, 4)
quanv_kernel(const float* __restrict__ x, float* __restrict__ out)
{
    extern __shared__ float smem[];
    float4* s_px = (float4*)smem;    // [14][NP] float4, single buffer
    float*  s_mg = smem;             // epilogue merge aliases px buffer

    const int tid   = threadIdx.x;
    const int p     = tid & 63;      // image-pair slot (imgs 2p, 2p+1)
    const int chalf = tid >> 6;      // 0: cols 0..6, 1: cols 7..13 (warp-uniform)

    const long imgBase = (long)blockIdx.x * IMGS;
    const float* xg = x + imgBase * 784;

    // granule base (j = tid + 128*it): img = j/14, v = j%14
    const int v0   = tid % 14;
    const int img0 = tid / 14;
    const int off0 = img0 * 784 + v0 * 4;

    // prefetch tile 0 into registers
    float4 stage[14];
    {
        int v = v0, off = off0;
        #pragma unroll
        for (int it = 0; it < 14; it++) {
            stage[it] = *(const float4*)(xg + off);
            off += 7064; v += 2;
            if (v >= 14) { v -= 14; off += 728; }
        }
    }

    ull accA[5], accB[5];
    #pragma unroll
    for (int q = 0; q < 5; q++) { accA[q] = 0ull; accB[q] = 0ull; }

    #pragma unroll 1
    for (int r = 0; r < 14; r++) {
        // store staged tile (14 STS.128), incremental indexing
        {
            int v = v0, img = img0;
            #pragma unroll
            for (int it = 0; it < 14; it++) {
                int pos = ((img & 1) << 6) | (img >> 1);    // pair-split permutation
                s_px[v * NP + pos] = stage[it];
                v += 2; img += 9;
                if (v >= 14) { v -= 14; img++; }
            }
        }
        __syncthreads();

        // prefetch next tile — latency hidden behind compute + other CTAs
        if (r < 13) {
            const float* srcT = xg + (r + 1) * 56;
            int v = v0, off = off0;
            #pragma unroll
            for (int it = 0; it < 14; it++) {
                stage[it] = *(const float4*)(srcT + off);
                off += 7064; v += 2;
                if (v >= 14) { v -= 14; off += 728; }
            }
        }

        if (chalf == 0) compute_tile<0>(s_px, r, p, accA, accB);
        else            compute_tile<7>(s_px, r, p, accA, accB);
        __syncthreads();
    }

    // unpack o-pair accumulators (no cross-lane reduce needed)
    float sA[10], sB[10];
    #pragma unroll
    for (int q = 0; q < 5; q++) {
        float2 fa = unpack2(accA[q]); sA[2 * q] = fa.x; sA[2 * q + 1] = fa.y;
        float2 fb = unpack2(accB[q]); sB[2 * q] = fb.x; sB[2 * q + 1] = fb.y;
    }

    // merge the two column-halves via shared (stride 21 per image slot)
    if (chalf == 1) {
        #pragma unroll
        for (int o = 0; o < 10; o++) {
            s_mg[p * 42 + o]      = sA[o];
            s_mg[p * 42 + 21 + o] = sB[o];
        }
    }
    __syncthreads();

    if (chalf == 0) {
        float l[20];
        #pragma unroll
        for (int o = 0; o < 10; o++) {
            l[o]      = sA[o] + s_mg[p * 42 + o]      + cbias[o];
            l[10 + o] = sB[o] + s_mg[p * 42 + 21 + o] + cbias[o];
        }
        #pragma unroll
        for (int im = 0; im < 2; im++) {
            float m = -INFINITY;
            #pragma unroll
            for (int o = 0; o < 10; o++) m = fmaxf(m, l[im * 10 + o]);
            float s = 0.f;
            #pragma unroll
            for (int o = 0; o < 10; o++) s += __expf(l[im * 10 + o] - m);
            float lse = m + __logf(s);
            #pragma unroll
            for (int o = 0; o < 10; o++) l[im * 10 + o] -= lse;
        }
        float4* op = (float4*)(out + (imgBase + 2 * p) * 10);   // 20 floats, aligned
        #pragma unroll
        for (int q = 0; q < 5; q++)
            op[q] = make_float4(l[q * 4], l[q * 4 + 1], l[q * 4 + 2], l[q * 4 + 3]);
    }
}

extern "C" void kernel_launch(void* const* d_in, const int* in_sizes, int n_in,
                              void* d_out, int out_size)
{
    const float* x = (const float*)d_in[0];
    const float* W = (const float*)d_in[1];
    const float* b = (const float*)d_in[2];
    float* out = (float*)d_out;

    // 1) repack W into o-pair layout in device scratch
    prep_kernel<<<19, 256>>>(W);

    // 2) move packed W + bias into constant memory (D2D async, capturable)
    void* wp_addr = nullptr;
    cudaGetSymbolAddress(&wp_addr, g_wp);
    cudaMemcpyToSymbolAsync(cW2, wp_addr, 784 * 6 * sizeof(ull), 0,
                            cudaMemcpyDeviceToDevice, 0);
    cudaMemcpyToSymbolAsync(cbias, b, 10 * sizeof(float), 0,
                            cudaMemcpyDeviceToDevice, 0);

    // 3) main kernel: grid 512 at 4 CTAs/SM -> single wave
    const int B = in_sizes[0] / 784;    // 65536
    const int grid = B / IMGS;          // 512

    cudaFuncSetAttribute(quanv_kernel,
                         cudaFuncAttributeMaxDynamicSharedMemorySize, SMEM_BYTES);
    quanv_kernel<<<grid, THREADS, SMEM_BYTES>>>(x, out);
}